// round 12
// baseline (speedup 1.0000x reference)
#include <cuda_runtime.h>

#define BATCH 32
#define HH 1024
#define WW 1024
#define WPR 32
#define WORDS_PER_IMG (HH * WPR)
#define NWORDS (BATCH * WORDS_PER_IMG)   // 1048576
#define NCELLS (BATCH * HH * WW)         // 33554432

#define TH 64
#define SH (TH + 16)
#define SW 34
#define NSIM  (BATCH * (HH / TH))        // 512 sim blocks
#define NCOPY (NCELLS / 2048)            // 16384 copy blocks (2048 cells each)
#define NUNP  (NWORDS / 128)             // 8192 unpack blocks (4096 cells each)
#define NQ    8388607                    // shifted quads at cells [3, NCELLS-1)

__device__ unsigned g_A[NWORDS];
__device__ unsigned g_B[NWORDS];
__device__ unsigned g_T[NWORDS];
__device__ unsigned long long g_live;
__device__ unsigned long long g_mism;
__device__ unsigned g_done;

// ---------------------------------------------------------------------------
// K1: pack initial floats -> bits (measured 23.7us). 16 cells via 4x LDG.128.
// ---------------------------------------------------------------------------
__global__ __launch_bounds__(256) void k_pack_ini(const float* __restrict__ ini) {
    int tid  = threadIdx.x;
    int lane = tid & 31;
    const float4* p = (const float4*)(ini + (size_t)blockIdx.x * 4096);
    float4 f0 = __ldcs(&p[tid * 4]);
    float4 f1 = __ldcs(&p[tid * 4 + 1]);
    float4 f2 = __ldcs(&p[tid * 4 + 2]);
    float4 f3 = __ldcs(&p[tid * 4 + 3]);
    unsigned half =
          (f0.x > 0.5f ? 1u : 0u)      | (f0.y > 0.5f ? 2u : 0u)
        | (f0.z > 0.5f ? 4u : 0u)      | (f0.w > 0.5f ? 8u : 0u)
        | (f1.x > 0.5f ? 16u : 0u)     | (f1.y > 0.5f ? 32u : 0u)
        | (f1.z > 0.5f ? 64u : 0u)     | (f1.w > 0.5f ? 128u : 0u)
        | (f2.x > 0.5f ? 256u : 0u)    | (f2.y > 0.5f ? 512u : 0u)
        | (f2.z > 0.5f ? 1024u : 0u)   | (f2.w > 0.5f ? 2048u : 0u)
        | (f3.x > 0.5f ? 4096u : 0u)   | (f3.y > 0.5f ? 8192u : 0u)
        | (f3.z > 0.5f ? 16384u : 0u)  | (f3.w > 0.5f ? 32768u : 0u);
    unsigned v = half << ((lane & 1) * 16);
    v |= __shfl_xor_sync(0xffffffffu, v, 1);
    if ((lane & 1) == 0)
        g_A[blockIdx.x * 128 + (tid >> 1)] = v;
}

// ---------------------------------------------------------------------------
// K2: blocks [0,512): 8-gen bit-sliced life (g_A -> g_B).
//     blocks [512,...): VECTORIZED target copy (shifted STG.128) + pack g_T.
// ---------------------------------------------------------------------------
__device__ __forceinline__ void hsum(unsigned l, unsigned m, unsigned r,
                                     unsigned& h0, unsigned& h1) {
    unsigned L = __funnelshift_l(l, m, 1);
    unsigned R = __funnelshift_r(m, r, 1);
    unsigned t = L ^ R;
    h0 = t ^ m;
    h1 = (L & R) | (t & m);
}

__device__ __forceinline__ unsigned gol_combine(
    unsigned h0a, unsigned h1a, unsigned h0b, unsigned h1b,
    unsigned h0c, unsigned h1c, unsigned bm) {
    unsigned t  = h0a ^ h0b;
    unsigned s0 = t ^ h0c;
    unsigned c1 = (h0a & h0b) | (t & h0c);
    unsigned u  = h1a ^ h1b;
    unsigned p  = u ^ h1c;
    unsigned q  = (h1a & h1b) | (u & h1c);
    unsigned s1 = p ^ c1;
    unsigned c2 = p & c1;
    unsigned eq3 = s0 & s1 & ~(q | c2);
    unsigned eq4 = (q ^ c2) & ~(s0 | s1);
    return eq3 | (bm & eq4);
}

__global__ __launch_bounds__(256) void k_life_tgt(const float* __restrict__ tgt,
                                                  float* __restrict__ out_tgt) {
    int tid  = threadIdx.x;
    int lane = tid & 31;

    if (blockIdx.x >= NSIM) {
        // ---------------- vectorized target copy + pack role ----------------
        int t = (blockIdx.x - NSIM) * 256 + tid;   // handles cells [8t, 8t+8)
        const float4* t4 = (const float4*)tgt;

        float4 f1 = t4[2 * t];
        float4 f2 = t4[2 * t + 1];
        float4 f3 = make_float4(0.f, 0.f, 0.f, 0.f);
        if (2 * t + 2 < NCELLS / 4) f3 = t4[2 * t + 2];

        *(float4*)(out_tgt + 8 * t + 3) = make_float4(f1.w, f2.x, f2.y, f2.z);
        if (8 * t + 7 != NCELLS - 1)
            *(float4*)(out_tgt + 8 * t + 7) = make_float4(f2.w, f3.x, f3.y, f3.z);
        else
            out_tgt[NCELLS - 1] = f2.w;
        if (t == 0) { out_tgt[0] = f1.x; out_tgt[1] = f1.y; out_tgt[2] = f1.z; }

        unsigned byte =
              (f1.x > 0.5f ? 1u : 0u)  | (f1.y > 0.5f ? 2u : 0u)
            | (f1.z > 0.5f ? 4u : 0u)  | (f1.w > 0.5f ? 8u : 0u)
            | (f2.x > 0.5f ? 16u : 0u) | (f2.y > 0.5f ? 32u : 0u)
            | (f2.z > 0.5f ? 64u : 0u) | (f2.w > 0.5f ? 128u : 0u);
        unsigned v = byte << ((lane & 3) * 8);
        v |= __shfl_xor_sync(0xffffffffu, v, 1);
        v |= __shfl_xor_sync(0xffffffffu, v, 2);
        if ((lane & 3) == 0) g_T[t >> 2] = v;
        return;
    }

    // ---------------- life simulation role ----------------
    __shared__ unsigned sb[2][SH][SW];

    int tile = blockIdx.x;
    int b    = tile >> 4;
    int ty   = tile & 15;
    int r0   = ty * TH;

    const unsigned* img = g_A + b * WORDS_PER_IMG;

    for (int s = tid; s < SH; s += 256) {
        sb[0][s][0] = 0u; sb[0][s][33] = 0u;
        sb[1][s][0] = 0u; sb[1][s][33] = 0u;
    }
    for (int idx = tid; idx < SH * 32; idx += 256) {
        int s  = idx >> 5;
        int c  = idx & 31;
        int gr = r0 - 8 + s;
        unsigned v = ((unsigned)gr < (unsigned)HH) ? img[gr * WPR + c] : 0u;
        sb[0][s][c + 1] = v;
    }
    __syncthreads();

    int c      = tid & 31;
    int strip  = tid >> 5;
    int rstart = 1 + strip * 10;
    int rend   = (rstart + 10 < 79) ? (rstart + 10) : 79;

    #pragma unroll
    for (int g = 0; g < 8; ++g) {
        int cur = g & 1, nxt = cur ^ 1;

        unsigned h0a, h1a, h0b, h1b, h0c, h1c;
        hsum(sb[cur][rstart - 1][c], sb[cur][rstart - 1][c + 1], sb[cur][rstart - 1][c + 2], h0a, h1a);
        unsigned bm = sb[cur][rstart][c + 1];
        hsum(sb[cur][rstart][c], bm, sb[cur][rstart][c + 2], h0b, h1b);

        for (int r = rstart; r < rend; ++r) {
            unsigned nl = sb[cur][r + 1][c];
            unsigned nm = sb[cur][r + 1][c + 1];
            unsigned nr = sb[cur][r + 1][c + 2];
            hsum(nl, nm, nr, h0c, h1c);

            unsigned next = gol_combine(h0a, h1a, h0b, h1b, h0c, h1c, bm);
            if ((unsigned)(r0 - 8 + r) >= (unsigned)HH) next = 0u;
            sb[nxt][r][c + 1] = next;

            h0a = h0b; h1a = h1b;
            h0b = h0c; h1b = h1c;
            bm  = nm;
        }
        __syncthreads();
    }

    unsigned* dst = g_B + b * WORDS_PER_IMG;
    for (int idx = tid; idx < TH * 32; idx += 256) {
        int s  = idx >> 5;
        int cc = idx & 31;
        dst[(r0 + s) * WPR + cc] = sb[0][8 + s][cc + 1];
    }
}

// ---------------------------------------------------------------------------
// K3: smem-staged vectorized unpack + popc reduce + finalize/self-reset.
// ---------------------------------------------------------------------------
__global__ __launch_bounds__(256) void k_unpack_reduce(float* __restrict__ out) {
    __shared__ unsigned sw[130];
    __shared__ int sh_live[8], sh_mism[8];
    int tid  = threadIdx.x;
    int lane = tid & 31;
    int wrp  = tid >> 5;
    int blk  = blockIdx.x;
    int base = blk * 128;
    float* outs = out + 1;

    int live = 0, mism = 0;
    if (tid < 128) {
        unsigned w = g_B[base + tid];
        unsigned t = g_T[base + tid];
        live = __popc(w);
        mism = __popc(w ^ t);
        sw[tid] = w;
    } else if (tid == 128) {
        sw[128] = (base + 128 < NWORDS) ? g_B[base + 128] : 0u;
    }
    __syncthreads();

    #pragma unroll
    for (int p = 0; p < 4; ++p) {
        int k      = p * 256 + tid;
        int Q      = blk * 1024 + k;
        int bitpos = 3 + 4 * k;
        unsigned lo = sw[bitpos >> 5];
        unsigned hi = sw[(bitpos >> 5) + 1];
        unsigned nib = __funnelshift_r(lo, hi, bitpos & 31) & 0xFu;
        if (Q < NQ) {
            float4 gq;
            gq.x = __uint_as_float((nib & 1u)        * 0x3f800000u);
            gq.y = __uint_as_float(((nib >> 1) & 1u) * 0x3f800000u);
            gq.z = __uint_as_float(((nib >> 2) & 1u) * 0x3f800000u);
            gq.w = __uint_as_float(((nib >> 3) & 1u) * 0x3f800000u);
            *(float4*)(outs + (size_t)base * 32 + bitpos) = gq;
        } else {
            outs[NCELLS - 1] = __uint_as_float((nib & 1u) * 0x3f800000u);
        }
        if (Q == 0) {
            unsigned w = sw[0];
            outs[0] = __uint_as_float((w & 1u)        * 0x3f800000u);
            outs[1] = __uint_as_float(((w >> 1) & 1u) * 0x3f800000u);
            outs[2] = __uint_as_float(((w >> 2) & 1u) * 0x3f800000u);
        }
    }

    #pragma unroll
    for (int o = 16; o > 0; o >>= 1) {
        live += __shfl_down_sync(0xffffffffu, live, o);
        mism += __shfl_down_sync(0xffffffffu, mism, o);
    }
    if (lane == 0) { sh_live[wrp] = live; sh_mism[wrp] = mism; }
    __syncthreads();
    if (tid == 0) {
        int L = 0, M = 0;
        #pragma unroll
        for (int k = 0; k < 8; ++k) { L += sh_live[k]; M += sh_mism[k]; }
        atomicAdd(&g_live, (unsigned long long)L);
        atomicAdd(&g_mism, (unsigned long long)M);
        __threadfence();
        unsigned prev = atomicAdd(&g_done, 1u);
        if (prev == (unsigned)(NUNP - 1)) {
            unsigned long long mt = atomicAdd(&g_mism, 0ull);
            unsigned long long lt = atomicAdd(&g_live, 0ull);
            out[0]              = (float)((double)mt / (double)NCELLS);  // loss
            out[1 + 2 * NCELLS] = (float)lt;                             // live_cells
            out[2 + 2 * NCELLS] = mt ? 1.0f : 0.0f;                      // max_abs_error
            g_live = 0ull; g_mism = 0ull;                                // replay reset
            __threadfence();
            g_done = 0u;
        }
    }
}

extern "C" void kernel_launch(void* const* d_in, const int* in_sizes, int n_in,
                              void* d_out, int out_size) {
    const float* initial = (const float*)d_in[0];
    const float* target  = (const float*)d_in[1];
    (void)in_sizes; (void)n_in; (void)out_size;   // generations fixed at 8

    float* out     = (float*)d_out;
    float* out_tgt = out + 1 + NCELLS;

    k_pack_ini<<<NCELLS / 4096, 256>>>(initial);
    k_life_tgt<<<NSIM + NCOPY, 256>>>(target, out_tgt);
    k_unpack_reduce<<<NUNP, 256>>>(out);
}

// round 13
// speedup vs baseline: 1.1057x; 1.1057x over previous
#include <cuda_runtime.h>

#define BATCH 32
#define HH 1024
#define WW 1024
#define WPR 32
#define WORDS_PER_IMG (HH * WPR)
#define NWORDS (BATCH * WORDS_PER_IMG)   // 1048576
#define NCELLS (BATCH * HH * WW)         // 33554432

#define TH 64
#define SH (TH + 16)
#define SW 34
#define NSIM  (BATCH * (HH / TH))        // 512 sim blocks
#define NCOPY (NCELLS / 2048)            // 16384 copy blocks
#define NUNP  (NWORDS / 128)             // 8192 unpack blocks
#define NQ    8388607                    // shifted quads at cells [3, NCELLS-1)

__device__ unsigned g_A[NWORDS];
__device__ unsigned g_B[NWORDS];
__device__ unsigned g_T[NWORDS];
__device__ unsigned long long g_live;
__device__ unsigned long long g_mism;
__device__ unsigned g_done;

// ---------------------------------------------------------------------------
// K1: pack initial floats -> bits. 16 cells via 4x LDG.128. Triggers PDL early.
// ---------------------------------------------------------------------------
__global__ __launch_bounds__(256) void k_pack_ini(const float* __restrict__ ini) {
    cudaTriggerProgrammaticLaunchCompletion();
    int tid  = threadIdx.x;
    int lane = tid & 31;
    const float4* p = (const float4*)(ini + (size_t)blockIdx.x * 4096);
    float4 f0 = __ldcs(&p[tid * 4]);
    float4 f1 = __ldcs(&p[tid * 4 + 1]);
    float4 f2 = __ldcs(&p[tid * 4 + 2]);
    float4 f3 = __ldcs(&p[tid * 4 + 3]);
    unsigned half =
          (f0.x > 0.5f ? 1u : 0u)      | (f0.y > 0.5f ? 2u : 0u)
        | (f0.z > 0.5f ? 4u : 0u)      | (f0.w > 0.5f ? 8u : 0u)
        | (f1.x > 0.5f ? 16u : 0u)     | (f1.y > 0.5f ? 32u : 0u)
        | (f1.z > 0.5f ? 64u : 0u)     | (f1.w > 0.5f ? 128u : 0u)
        | (f2.x > 0.5f ? 256u : 0u)    | (f2.y > 0.5f ? 512u : 0u)
        | (f2.z > 0.5f ? 1024u : 0u)   | (f2.w > 0.5f ? 2048u : 0u)
        | (f3.x > 0.5f ? 4096u : 0u)   | (f3.y > 0.5f ? 8192u : 0u)
        | (f3.z > 0.5f ? 16384u : 0u)  | (f3.w > 0.5f ? 32768u : 0u);
    unsigned v = half << ((lane & 1) * 16);
    v |= __shfl_xor_sync(0xffffffffu, v, 1);
    if ((lane & 1) == 0)
        g_A[blockIdx.x * 128 + (tid >> 1)] = v;
}

// ---------------------------------------------------------------------------
// K2: blocks [0,512): 8-gen bit-sliced life (gridsync, then g_A -> g_B).
//     blocks [512,...): target copy + pack g_T (NO dependence on K1 -> no sync).
// ---------------------------------------------------------------------------
__device__ __forceinline__ void hsum(unsigned l, unsigned m, unsigned r,
                                     unsigned& h0, unsigned& h1) {
    unsigned L = __funnelshift_l(l, m, 1);
    unsigned R = __funnelshift_r(m, r, 1);
    unsigned t = L ^ R;
    h0 = t ^ m;
    h1 = (L & R) | (t & m);
}

__device__ __forceinline__ unsigned gol_combine(
    unsigned h0a, unsigned h1a, unsigned h0b, unsigned h1b,
    unsigned h0c, unsigned h1c, unsigned bm) {
    unsigned t  = h0a ^ h0b;
    unsigned s0 = t ^ h0c;
    unsigned c1 = (h0a & h0b) | (t & h0c);
    unsigned u  = h1a ^ h1b;
    unsigned p  = u ^ h1c;
    unsigned q  = (h1a & h1b) | (u & h1c);
    unsigned s1 = p ^ c1;
    unsigned c2 = p & c1;
    unsigned eq3 = s0 & s1 & ~(q | c2);
    unsigned eq4 = (q ^ c2) & ~(s0 | s1);
    return eq3 | (bm & eq4);
}

__global__ __launch_bounds__(256) void k_life_tgt(const float* __restrict__ tgt,
                                                  float* __restrict__ out_tgt) {
    cudaTriggerProgrammaticLaunchCompletion();
    int tid  = threadIdx.x;
    int lane = tid & 31;
    int wrp  = tid >> 5;

    if (blockIdx.x >= NSIM) {
        // ---------------- target copy + pack role (independent of K1) -------
        int cblk = blockIdx.x - NSIM;
        int warp = cblk * 8 + wrp;
        unsigned cb = (unsigned)warp * 256u;
        unsigned wb = (unsigned)warp * 8u;

        float ft[8];
        #pragma unroll
        for (int k = 0; k < 8; ++k) ft[k] = tgt[cb + 32u * k + lane];
        #pragma unroll
        for (int k = 0; k < 8; ++k) out_tgt[cb + 32u * k + lane] = ft[k];

        unsigned myw = 0u;
        #pragma unroll
        for (int k = 0; k < 8; ++k) {
            unsigned bT = __ballot_sync(0xffffffffu, ft[k] > 0.5f);
            if (lane == k) myw = bT;
        }
        if (lane < 8) g_T[wb + lane] = myw;
        return;
    }

    // ---------------- life simulation role: wait for K1's g_A ----------------
    cudaGridDependencySynchronize();

    __shared__ unsigned sb[2][SH][SW];

    int tile = blockIdx.x;
    int b    = tile >> 4;
    int ty   = tile & 15;
    int r0   = ty * TH;

    const unsigned* img = g_A + b * WORDS_PER_IMG;

    for (int s = tid; s < SH; s += 256) {
        sb[0][s][0] = 0u; sb[0][s][33] = 0u;
        sb[1][s][0] = 0u; sb[1][s][33] = 0u;
    }
    for (int idx = tid; idx < SH * 32; idx += 256) {
        int s  = idx >> 5;
        int c  = idx & 31;
        int gr = r0 - 8 + s;
        unsigned v = ((unsigned)gr < (unsigned)HH) ? img[gr * WPR + c] : 0u;
        sb[0][s][c + 1] = v;
    }
    __syncthreads();

    int c      = tid & 31;
    int strip  = tid >> 5;
    int rstart = 1 + strip * 10;
    int rend   = (rstart + 10 < 79) ? (rstart + 10) : 79;

    #pragma unroll
    for (int g = 0; g < 8; ++g) {
        int cur = g & 1, nxt = cur ^ 1;

        unsigned h0a, h1a, h0b, h1b, h0c, h1c;
        hsum(sb[cur][rstart - 1][c], sb[cur][rstart - 1][c + 1], sb[cur][rstart - 1][c + 2], h0a, h1a);
        unsigned bm = sb[cur][rstart][c + 1];
        hsum(sb[cur][rstart][c], bm, sb[cur][rstart][c + 2], h0b, h1b);

        for (int r = rstart; r < rend; ++r) {
            unsigned nl = sb[cur][r + 1][c];
            unsigned nm = sb[cur][r + 1][c + 1];
            unsigned nr = sb[cur][r + 1][c + 2];
            hsum(nl, nm, nr, h0c, h1c);

            unsigned next = gol_combine(h0a, h1a, h0b, h1b, h0c, h1c, bm);
            if ((unsigned)(r0 - 8 + r) >= (unsigned)HH) next = 0u;
            sb[nxt][r][c + 1] = next;

            h0a = h0b; h1a = h1b;
            h0b = h0c; h1b = h1c;
            bm  = nm;
        }
        __syncthreads();
    }

    unsigned* dst = g_B + b * WORDS_PER_IMG;
    for (int idx = tid; idx < TH * 32; idx += 256) {
        int s  = idx >> 5;
        int cc = idx & 31;
        dst[(r0 + s) * WPR + cc] = sb[0][8 + s][cc + 1];
    }
}

// ---------------------------------------------------------------------------
// K3: smem-staged vectorized unpack + popc reduce + finalize/self-reset.
// ---------------------------------------------------------------------------
__global__ __launch_bounds__(256) void k_unpack_reduce(float* __restrict__ out) {
    cudaGridDependencySynchronize();   // needs g_B (sim) and g_T (copy)

    __shared__ unsigned sw[130];
    __shared__ int sh_live[8], sh_mism[8];
    int tid  = threadIdx.x;
    int lane = tid & 31;
    int wrp  = tid >> 5;
    int blk  = blockIdx.x;
    int base = blk * 128;
    float* outs = out + 1;

    int live = 0, mism = 0;
    if (tid < 128) {
        unsigned w = g_B[base + tid];
        unsigned t = g_T[base + tid];
        live = __popc(w);
        mism = __popc(w ^ t);
        sw[tid] = w;
    } else if (tid == 128) {
        sw[128] = (base + 128 < NWORDS) ? g_B[base + 128] : 0u;
    }
    __syncthreads();

    #pragma unroll
    for (int p = 0; p < 4; ++p) {
        int k      = p * 256 + tid;
        int Q      = blk * 1024 + k;
        int bitpos = 3 + 4 * k;
        unsigned lo = sw[bitpos >> 5];
        unsigned hi = sw[(bitpos >> 5) + 1];
        unsigned nib = __funnelshift_r(lo, hi, bitpos & 31) & 0xFu;
        if (Q < NQ) {
            float4 gq;
            gq.x = __uint_as_float((nib & 1u)        * 0x3f800000u);
            gq.y = __uint_as_float(((nib >> 1) & 1u) * 0x3f800000u);
            gq.z = __uint_as_float(((nib >> 2) & 1u) * 0x3f800000u);
            gq.w = __uint_as_float(((nib >> 3) & 1u) * 0x3f800000u);
            *(float4*)(outs + (size_t)base * 32 + bitpos) = gq;
        } else {
            outs[NCELLS - 1] = __uint_as_float((nib & 1u) * 0x3f800000u);
        }
        if (Q == 0) {
            unsigned w = sw[0];
            outs[0] = __uint_as_float((w & 1u)        * 0x3f800000u);
            outs[1] = __uint_as_float(((w >> 1) & 1u) * 0x3f800000u);
            outs[2] = __uint_as_float(((w >> 2) & 1u) * 0x3f800000u);
        }
    }

    #pragma unroll
    for (int o = 16; o > 0; o >>= 1) {
        live += __shfl_down_sync(0xffffffffu, live, o);
        mism += __shfl_down_sync(0xffffffffu, mism, o);
    }
    if (lane == 0) { sh_live[wrp] = live; sh_mism[wrp] = mism; }
    __syncthreads();
    if (tid == 0) {
        int L = 0, M = 0;
        #pragma unroll
        for (int k = 0; k < 8; ++k) { L += sh_live[k]; M += sh_mism[k]; }
        atomicAdd(&g_live, (unsigned long long)L);
        atomicAdd(&g_mism, (unsigned long long)M);
        __threadfence();
        unsigned prev = atomicAdd(&g_done, 1u);
        if (prev == (unsigned)(NUNP - 1)) {
            unsigned long long mt = atomicAdd(&g_mism, 0ull);
            unsigned long long lt = atomicAdd(&g_live, 0ull);
            out[0]              = (float)((double)mt / (double)NCELLS);  // loss
            out[1 + 2 * NCELLS] = (float)lt;                             // live_cells
            out[2 + 2 * NCELLS] = mt ? 1.0f : 0.0f;                      // max_abs_error
            g_live = 0ull; g_mism = 0ull;                                // replay reset
            __threadfence();
            g_done = 0u;
        }
    }
}

extern "C" void kernel_launch(void* const* d_in, const int* in_sizes, int n_in,
                              void* d_out, int out_size) {
    const float* initial = (const float*)d_in[0];
    const float* target  = (const float*)d_in[1];
    (void)in_sizes; (void)n_in; (void)out_size;   // generations fixed at 8

    float* out     = (float*)d_out;
    float* out_tgt = out + 1 + NCELLS;

    // K1: normal launch
    k_pack_ini<<<NCELLS / 4096, 256>>>(initial);

    // K2, K3: PDL launches (may begin dispatch during predecessor's tail)
    cudaLaunchAttribute attr[1];
    attr[0].id = cudaLaunchAttributeProgrammaticStreamSerialization;
    attr[0].val.programmaticStreamSerializationAllowed = 1;

    {
        cudaLaunchConfig_t cfg = {};
        cfg.gridDim  = dim3(NSIM + NCOPY);
        cfg.blockDim = dim3(256);
        cfg.attrs    = attr;
        cfg.numAttrs = 1;
        cudaLaunchKernelEx(&cfg, k_life_tgt, target, out_tgt);
    }
    {
        cudaLaunchConfig_t cfg = {};
        cfg.gridDim  = dim3(NUNP);
        cfg.blockDim = dim3(256);
        cfg.attrs    = attr;
        cfg.numAttrs = 1;
        cudaLaunchKernelEx(&cfg, k_unpack_reduce, out);
    }
}